// round 14
// baseline (speedup 1.0000x reference)
#include <cuda_runtime.h>
#include <cstdint>

// ---------------- problem dims ----------------
#define BB 8
#define NN 256
#define NI 36
#define SS 64
#define IN_D 1024
#define QUE_D 1024
#define IMG_D 2048
#define SEM_D 512
#define PP 512
#define CATD 1536
#define OUTD 1024
#define ROWS (BB*NN)
#define MROWS_I (BB*NI)   // 288
#define MROWS_S (BB*SS)   // 512
#define M1 (ROWS*PP)      // 1048576

// ---------------- scratch ----------------
__device__ float g_qproj_img[BB*PP];
__device__ float g_qproj_sem[BB*PP];
__device__ float g_ip[MROWS_I*PP];
__device__ float g_sp[MROWS_S*PP];
__device__ float g_img_ctx[ROWS*IMG_D];
__device__ float g_sem_ctx[ROWS*SEM_D];
__device__ float g_cat[ROWS*CATD];
__device__ float g_gcat[ROWS*CATD];
__device__ float g_part[12*1024*1024];    // 48MB partial-sum scratch
// tf32-pre-rounded copies
__device__ float g_h_r[ROWS*IN_D];
__device__ float g_img_r[MROWS_I*IMG_D];
__device__ float g_sem_r[MROWS_S*SEM_D];
__device__ float g_Wcif_r[IN_D*PP];
__device__ float g_Wcsf_r[IN_D*PP];
__device__ float g_Wcii_r[IMG_D*PP];
__device__ float g_Wcsn_r[SEM_D*PP];
__device__ float g_Wfg_r[IN_D*PP];
__device__ float g_Wig_r[IMG_D*PP];
__device__ float g_Wsg_r[SEM_D*PP];
__device__ float g_Wgate_r[CATD*CATD];
__device__ float g_Wout_r[CATD*OUTD];

// ---------------- helpers ----------------
__device__ __forceinline__ float tanh_fast(float x) {
    float y; asm("tanh.approx.f32 %0, %1;" : "=f"(y) : "f"(x)); return y;
}
__device__ __forceinline__ float sigmoid_fast(float x) {
    return 1.0f / (1.0f + __expf(-x));
}
__device__ __forceinline__ float f2tf_f(float x) {
    uint32_t r; asm("cvt.rna.tf32.f32 %0, %1;" : "=r"(r) : "f"(x));
    return __uint_as_float(r);
}
__device__ __forceinline__ void mma8(float* c, const uint32_t* a, uint32_t b0, uint32_t b1) {
    asm("mma.sync.aligned.m16n8k8.row.col.f32.tf32.tf32.f32 "
        "{%0,%1,%2,%3}, {%4,%5,%6,%7}, {%8,%9}, {%0,%1,%2,%3};"
        : "+f"(c[0]), "+f"(c[1]), "+f"(c[2]), "+f"(c[3])
        : "r"(a[0]), "r"(a[1]), "r"(a[2]), "r"(a[3]), "r"(b0), "r"(b1));
}
__device__ __forceinline__ uint32_t smem_u32(const void* p) {
    uint32_t a;
    asm("{ .reg .u64 t; cvta.to.shared.u64 t, %1; cvt.u32.u64 %0, t; }" : "=r"(a) : "l"(p));
    return a;
}
#define CP_ASYNC16(dst, src) \
    asm volatile("cp.async.cg.shared.global [%0], [%1], 16;" :: "r"(dst), "l"(src))
#define CP_COMMIT() asm volatile("cp.async.commit_group;" ::: "memory")
#define CP_WAIT1()  asm volatile("cp.async.wait_group 1;" ::: "memory")

// ---------------- GEMM core (shared device body): CTA 128x128, 8 warps of 64x32 ----------------
struct TaskDesc {
    const float* A; const float* W; const float* bias; const float* extra;
    float* C; int lda, ldw, lde, ldc, M, K, mode, rnd;
};
struct TaskList { TaskDesc t[9]; };

#define STG_FLOATS 8192          // 32KB/stage
#define GEMM_SMEM (3 * STG_FLOATS * 4)

__device__ __forceinline__ void gemm_body(const TaskDesc& T, int bx, int by, float* sm) {
    const int m0 = by * 128;
    if (m0 >= T.M) return;
    const int n0 = bx * 128;
    const uint32_t smb = smem_u32(sm);

    const int tid = threadIdx.x;
    const int lane = tid & 31;
    const int wid = tid >> 5;
    const int wr = wid >> 2;
    const int wc = wid & 3;

    const int arow = tid >> 3;
    const int ac   = tid & 7;
    const int bk   = tid >> 3;
    const int bc0  = tid & 7;

    uint32_t adst[4], bdst[4];
#pragma unroll
    for (int s = 0; s < 4; s++) {
        int row = arow + 32 * s;
        adst[s] = (uint32_t)(row * 128 + ((ac ^ (row & 7)) << 4));
    }
#pragma unroll
    for (int j = 0; j < 4; j++) {
        int c = bc0 + 8 * j;
        bdst[j] = (uint32_t)(16384 + bk * 512 + ((c ^ ((bk & 3) << 1)) << 4));
    }
    const float* Asrc[4];
#pragma unroll
    for (int s = 0; s < 4; s++) {
        int r = m0 + arow + 32 * s;
        if (r >= T.M) r = T.M - 1;
        Asrc[s] = T.A + (size_t)r * T.lda + ac * 4;
    }
    const float* Bsrc = T.W + (size_t)bk * T.ldw + n0 + bc0 * 4;

    const int S = T.K >> 5;

    auto issue_stage = [&](int i) {
        uint32_t base = smb + (uint32_t)(i % 3) * (STG_FLOATS * 4);
        int k0 = i << 5;
#pragma unroll
        for (int s = 0; s < 4; s++) CP_ASYNC16(base + adst[s], Asrc[s] + k0);
        const float* wsrc = Bsrc + (size_t)k0 * T.ldw;
#pragma unroll
        for (int j = 0; j < 4; j++) CP_ASYNC16(base + bdst[j], wsrc + 8 * j * 4);
    };

    float acc[4][4][4];
#pragma unroll
    for (int i = 0; i < 4; i++)
#pragma unroll
        for (int t = 0; t < 4; t++)
#pragma unroll
            for (int r = 0; r < 4; r++) acc[i][t][r] = 0.0f;

    issue_stage(0); CP_COMMIT();
    if (S > 1) issue_stage(1);
    CP_COMMIT();

    const int lrow = lane >> 2;
    const int lk   = lane & 3;

    for (int i = 0; i < S; i++) {
        CP_WAIT1();
        __syncthreads();

        const float* base = sm + (size_t)(i % 3) * STG_FLOATS;
#pragma unroll
        for (int kk = 0; kk < 4; kk++) {
            uint32_t a[4][4], b[4][2];
#pragma unroll
            for (int ii = 0; ii < 4; ii++) {
                int mt = wr * 4 + ii;
#pragma unroll
                for (int r = 0; r < 4; r++) {
                    int row = mt * 16 + lrow + 8 * (r & 1);
                    int k = kk * 8 + lk + 4 * (r >> 1);
                    a[ii][r] = __float_as_uint(
                        base[row * 32 + (((k >> 2) ^ (row & 7)) << 2) + (k & 3)]);
                }
            }
#pragma unroll
            for (int t = 0; t < 4; t++) {
                int nt = wc * 4 + t;
#pragma unroll
                for (int r = 0; r < 2; r++) {
                    int k = kk * 8 + lk + 4 * r;
                    int n = nt * 8 + lrow;
                    b[t][r] = __float_as_uint(
                        base[4096 + k * 128 + (((n >> 2) ^ ((k & 3) << 1)) << 2) + (n & 3)]);
                }
            }
#pragma unroll
            for (int ii = 0; ii < 4; ii++)
#pragma unroll
                for (int t = 0; t < 4; t++)
                    mma8(acc[ii][t], a[ii], b[t][0], b[t][1]);
        }

        if (i + 2 < S) issue_stage(i + 2);
        CP_COMMIT();
    }

#pragma unroll
    for (int i = 0; i < 4; i++) {
        int rbase = m0 + wr * 64 + i * 16 + lrow;
#pragma unroll
        for (int t = 0; t < 4; t++) {
            int cb = n0 + wc * 32 + t * 8 + 2 * lk;
#pragma unroll
            for (int hh = 0; hh < 2; hh++) {
                int r = rbase + 8 * hh;
                if (r >= T.M) continue;
                float c0 = acc[i][t][2 * hh], c1 = acc[i][t][2 * hh + 1];
                float2 v;
                if (T.mode == 3) {
                    v = make_float2(c0, c1);
                } else if (T.mode == 0) {
                    float2 bs = *(const float2*)(T.bias + cb);
                    v = make_float2(c0 + bs.x, c1 + bs.y);
                } else if (T.mode == 1) {
                    float2 ev = *(const float2*)(T.extra + (size_t)(r >> 8) * T.lde + cb);
                    v = make_float2(c0 + ev.x, c1 + ev.y);
                } else {
                    float2 bs = *(const float2*)(T.bias + cb);
                    float2 ev = *(const float2*)(T.extra + (size_t)r * T.lde + cb);
                    v = make_float2(sigmoid_fast(c0 + bs.x) * ev.x,
                                    sigmoid_fast(c1 + bs.y) * ev.y);
                }
                if (T.rnd) { v.x = f2tf_f(v.x); v.y = f2tf_f(v.y); }
                *(float2*)(T.C + (size_t)r * T.ldc + cb) = v;
            }
        }
    }
}

__global__ __launch_bounds__(256, 2)
void mma_gemm(TaskList TL) {
    extern __shared__ float sm[];
    gemm_body(TL.t[blockIdx.z], blockIdx.x, blockIdx.y, sm);
}

// ---------------- partial-sum reduce + epilogue ----------------
struct RTask {
    const float* p; int nparts; int pstride;
    const float* bias; const float* extra; int lde;
    float* o; int ldo; int M, N, mode, rnd;
};
struct RList { RTask t[4]; };
__global__ __launch_bounds__(256)
void reduce_k(RList L) {
    RTask R = L.t[blockIdx.y];
    const int n4 = R.N >> 2;
    const int total = R.M * n4;
    for (int i = blockIdx.x * 256 + threadIdx.x; i < total; i += gridDim.x * 256) {
        int r = i / n4, c4 = i - r * n4;
        const float4* pp = (const float4*)R.p + (size_t)r * n4 + c4;
        float4 s = *pp;
        for (int q = 1; q < R.nparts; q++) {
            float4 v = *(const float4*)((const float*)pp + (size_t)q * R.pstride);
            s.x += v.x; s.y += v.y; s.z += v.z; s.w += v.w;
        }
        if (R.mode == 0) {
            float4 bv = *(const float4*)(R.bias + c4 * 4);
            s.x += bv.x; s.y += bv.y; s.z += bv.z; s.w += bv.w;
        } else if (R.mode == 1) {
            float4 ev = *(const float4*)(R.extra + (size_t)(r >> 8) * R.lde + c4 * 4);
            s.x += ev.x; s.y += ev.y; s.z += ev.z; s.w += ev.w;
        } else {
            float4 bv = *(const float4*)(R.bias + c4 * 4);
            float4 ev = *(const float4*)(R.extra + (size_t)r * R.lde + c4 * 4);
            s.x = sigmoid_fast(s.x + bv.x) * ev.x;
            s.y = sigmoid_fast(s.y + bv.y) * ev.y;
            s.z = sigmoid_fast(s.z + bv.z) * ev.z;
            s.w = sigmoid_fast(s.w + bv.w) * ev.w;
        }
        if (R.rnd) { s.x = f2tf_f(s.x); s.y = f2tf_f(s.y); s.z = f2tf_f(s.z); s.w = f2tf_f(s.w); }
        *(float4*)(R.o + (size_t)r * R.ldo + c4 * 4) = s;
    }
}

// ---------------- prep: tf32 rounding (8 tensors needed early) + qproj ----------------
struct PrepArgs {
    const float* src[8]; float* dst[8]; int n4[8];
    const float* que;
    const float* W1; const float* b1; float* o1;
    const float* W2; const float* b2; float* o2;
};
__global__ __launch_bounds__(256)
void prep_kernel(PrepArgs P) {
    const int g = blockIdx.x;
    const int tid = threadIdx.x;
    if (g < 1024) {
        int z = g >> 7;
        const float4* s = (const float4*)P.src[z];
        float4* d = (float4*)P.dst[z];
        int n4 = P.n4[z];
        for (int i = (g & 127) * 256 + tid; i < n4; i += 128 * 256) {
            float4 v = s[i];
            v.x = f2tf_f(v.x); v.y = f2tf_f(v.y); v.z = f2tf_f(v.z); v.w = f2tf_f(v.w);
            d[i] = v;
        }
    } else {
        int g2 = g - 1024;                 // [0,32)
        int z  = g2 >> 4;
        int b  = (g2 >> 1) & 7;
        int j  = (g2 & 1) * 256 + tid;
        const float* Wsub = z ? P.W2 : P.W1;
        const float* bias = z ? P.b2 : P.b1;
        float* out = z ? P.o2 : P.o1;
        const float* q = P.que + b * QUE_D;
        float a0 = 0.f, a1 = 0.f, a2 = 0.f, a3 = 0.f;
#pragma unroll 2
        for (int k = 0; k < QUE_D; k += 4) {
            a0 = fmaf(q[k],     Wsub[(size_t)k * PP + j],       a0);
            a1 = fmaf(q[k + 1], Wsub[(size_t)(k + 1) * PP + j], a1);
            a2 = fmaf(q[k + 2], Wsub[(size_t)(k + 2) * PP + j], a2);
            a3 = fmaf(q[k + 3], Wsub[(size_t)(k + 3) * PP + j], a3);
        }
        out[b * PP + j] = bias[j] + ((a0 + a1) + (a2 + a3));
    }
}

// ---------------- attention body (unchanged from R13) ----------------
template <int KN, int D, int RSPLIT>
__device__ __forceinline__ void att_body(int g,
        const float* __restrict__ np0, const float* __restrict__ np1,
        const float* __restrict__ qp,
        const float* __restrict__ kp,
        const float* __restrict__ kv, const float* __restrict__ w,
        float* __restrict__ ctx) {
    __shared__ __align__(16) float s_w[PP];
    __shared__ float s_logit[8][64];
    __shared__ float s_att[8][64];

    const int b = g >> 5;
    const int r0 = (g & 31) * 8;
    const int tid = threadIdx.x;
    const int wid = tid >> 5, lane = tid & 31;

    for (int i = tid; i < PP; i += 256) s_w[i] = w[i];

    const int row = b * NN + r0 + wid;
    float4 npv[4];
    const float4* nr0 = (const float4*)(np0 + (size_t)row * PP);
    const float4* nr1 = (const float4*)(np1 + (size_t)row * PP);
    const float4* qr  = (const float4*)(qp + (size_t)b * PP);
#pragma unroll
    for (int i = 0; i < 4; i++) {
        float4 x = nr0[lane + 32 * i];
        float4 y = nr1[lane + 32 * i];
        float4 q = qr[lane + 32 * i];
        npv[i] = make_float4((x.x + y.x) + q.x, (x.y + y.y) + q.y,
                             (x.z + y.z) + q.z, (x.w + y.w) + q.w);
    }
    __syncthreads();

    for (int k = 0; k < KN; k++) {
        const float4* kr = (const float4*)(kp + (size_t)(b * KN + k) * PP);
        float a0 = 0.f, a1 = 0.f, a2 = 0.f, a3 = 0.f;
        {
            float4 k0 = kr[lane],       w0 = ((const float4*)s_w)[lane];
            float4 k1 = kr[lane + 32],  w1 = ((const float4*)s_w)[lane + 32];
            float4 k2 = kr[lane + 64],  w2 = ((const float4*)s_w)[lane + 64];
            float4 k3 = kr[lane + 96],  w3 = ((const float4*)s_w)[lane + 96];
            a0 = fmaf(tanh_fast(npv[0].x + k0.x), w0.x, a0);
            a1 = fmaf(tanh_fast(npv[0].y + k0.y), w0.y, a1);
            a2 = fmaf(tanh_fast(npv[0].z + k0.z), w0.z, a2);
            a3 = fmaf(tanh_fast(npv[0].w + k0.w), w0.w, a3);
            a0 = fmaf(tanh_fast(npv[1].x + k1.x), w1.x, a0);
            a1 = fmaf(tanh_fast(npv[1].y + k1.y), w1.y, a1);
            a2 = fmaf(tanh_fast(npv[1].z + k1.z), w1.z, a2);
            a3 = fmaf(tanh_fast(npv[1].w + k1.w), w1.w, a3);
            a0 = fmaf(tanh_fast(npv[2].x + k2.x), w2.x, a0);
            a1 = fmaf(tanh_fast(npv[2].y + k2.y), w2.y, a1);
            a2 = fmaf(tanh_fast(npv[2].z + k2.z), w2.z, a2);
            a3 = fmaf(tanh_fast(npv[2].w + k2.w), w2.w, a3);
            a0 = fmaf(tanh_fast(npv[3].x + k3.x), w3.x, a0);
            a1 = fmaf(tanh_fast(npv[3].y + k3.y), w3.y, a1);
            a2 = fmaf(tanh_fast(npv[3].z + k3.z), w3.z, a2);
            a3 = fmaf(tanh_fast(npv[3].w + k3.w), w3.w, a3);
        }
        float acc = (a0 + a1) + (a2 + a3);
#pragma unroll
        for (int o = 16; o > 0; o >>= 1) acc += __shfl_xor_sync(0xffffffff, acc, o);
        if (lane == 0) s_logit[wid][k] = acc;
    }
    __syncwarp();

    {
        float l0 = (lane < KN) ? s_logit[wid][lane] : -1e30f;
        float l1 = (lane + 32 < KN) ? s_logit[wid][lane + 32] : -1e30f;
        float m = fmaxf(l0, l1);
#pragma unroll
        for (int o = 16; o > 0; o >>= 1) m = fmaxf(m, __shfl_xor_sync(0xffffffff, m, o));
        float e0 = (lane < KN) ? __expf(l0 - m) : 0.0f;
        float e1 = (lane + 32 < KN) ? __expf(l1 - m) : 0.0f;
        float sum = e0 + e1;
#pragma unroll
        for (int o = 16; o > 0; o >>= 1) sum += __shfl_xor_sync(0xffffffff, sum, o);
        float inv = 1.0f / sum;
        s_att[wid][lane] = e0 * inv;
        if (lane + 32 < 64) s_att[wid][lane + 32] = e1 * inv;
    }
    __syncthreads();

    const float4* kvb = (const float4*)(kv + (size_t)b * KN * D);
    if (RSPLIT) {
        const int half = tid >> 7;
        const int d4 = tid & 127;
        float4 a[4];
#pragma unroll
        for (int r = 0; r < 4; r++) a[r] = make_float4(0.f, 0.f, 0.f, 0.f);
        for (int k = 0; k < KN; k++) {
            float4 v = kvb[(size_t)k * (D / 4) + d4];
#pragma unroll
            for (int r = 0; r < 4; r++) {
                float at = s_att[half * 4 + r][k];
                a[r].x = fmaf(at, v.x, a[r].x);
                a[r].y = fmaf(at, v.y, a[r].y);
                a[r].z = fmaf(at, v.z, a[r].z);
                a[r].w = fmaf(at, v.w, a[r].w);
            }
        }
#pragma unroll
        for (int r = 0; r < 4; r++) {
            float4 o;
            o.x = f2tf_f(a[r].x); o.y = f2tf_f(a[r].y);
            o.z = f2tf_f(a[r].z); o.w = f2tf_f(a[r].w);
            *(float4*)(ctx + (size_t)(b * NN + r0 + half * 4 + r) * D + d4 * 4) = o;
        }
    } else {
        for (int d4 = tid; d4 < D / 4; d4 += 256) {
            float4 a[8];
#pragma unroll
            for (int r = 0; r < 8; r++) a[r] = make_float4(0.f, 0.f, 0.f, 0.f);
            for (int k = 0; k < KN; k++) {
                float4 v = kvb[(size_t)k * (D / 4) + d4];
#pragma unroll
                for (int r = 0; r < 8; r++) {
                    float at = s_att[r][k];
                    a[r].x = fmaf(at, v.x, a[r].x);
                    a[r].y = fmaf(at, v.y, a[r].y);
                    a[r].z = fmaf(at, v.z, a[r].z);
                    a[r].w = fmaf(at, v.w, a[r].w);
                }
            }
#pragma unroll
            for (int r = 0; r < 8; r++) {
                float4 o;
                o.x = f2tf_f(a[r].x); o.y = f2tf_f(a[r].y);
                o.z = f2tf_f(a[r].z); o.w = f2tf_f(a[r].w);
                *(float4*)(ctx + (size_t)(b * NN + r0 + r) * D + d4 * 4) = o;
            }
        }
    }
}

// ---------------- fat kernel: cat-f GEMM (0..127) + attention (128..639) + late-weight cvt (640..767) ----------------
struct AttArgs {
    const float* np0i; const float* np1i; const float* qpi;
    const float* ipb; const float* img; const float* w_ia; float* ictx;
    const float* np0s; const float* np1s; const float* qps;
    const float* spb; const float* sem; const float* w_sa; float* sctx;
    const float* csrc[4]; float* cdst[4]; int cn4[4];   // late weight cvts
};
__global__ __launch_bounds__(256, 2)
void att_catf(AttArgs A, TaskDesc g0, TaskDesc g1) {
    extern __shared__ float sm[];
    const int bid = blockIdx.x;
    if (bid < 128) {
        const TaskDesc& T = (bid < 64) ? g0 : g1;
        int w = bid & 63;
        gemm_body(T, w & 3, w >> 2, sm);
    } else if (bid < 384) {
        att_body<NI, IMG_D, 0>(bid - 128, A.np0i, A.np1i, A.qpi, A.ipb, A.img, A.w_ia, A.ictx);
    } else if (bid < 640) {
        att_body<SS, SEM_D, 1>(bid - 384, A.np0s, A.np1s, A.qps, A.spb, A.sem, A.w_sa, A.sctx);
    } else {
        int g2 = bid - 640;                // [0,128)
        int z = g2 >> 5;                   // 0..3
        const float4* s = (const float4*)A.csrc[z];
        float4* d = (float4*)A.cdst[z];
        int n4 = A.cn4[z];
        for (int i = (g2 & 31) * 256 + threadIdx.x; i < n4; i += 32 * 256) {
            float4 v = s[i];
            v.x = f2tf_f(v.x); v.y = f2tf_f(v.y); v.z = f2tf_f(v.z); v.w = f2tf_f(v.w);
            d[i] = v;
        }
    }
}

// ---------------- launch ----------------
extern "C" void kernel_launch(void* const* d_in, const int* in_sizes, int n_in,
                              void* d_out, int out_size) {
    const float* h      = (const float*)d_in[0];
    const float* img    = (const float*)d_in[1];
    const float* sem    = (const float*)d_in[2];
    const float* que    = (const float*)d_in[3];
    const float* W_cif  = (const float*)d_in[4];
    const float* b_cif  = (const float*)d_in[5];
    const float* W_cii  = (const float*)d_in[6];
    const float* b_cii  = (const float*)d_in[7];
    const float* w_ia   = (const float*)d_in[8];
    const float* W_csf  = (const float*)d_in[10];
    const float* b_csf  = (const float*)d_in[11];
    const float* W_csn  = (const float*)d_in[12];
    const float* b_csn  = (const float*)d_in[13];
    const float* w_sa   = (const float*)d_in[14];
    const float* W_ig   = (const float*)d_in[16];
    const float* b_ig   = (const float*)d_in[17];
    const float* W_sg   = (const float*)d_in[18];
    const float* b_sg   = (const float*)d_in[19];
    const float* W_fg   = (const float*)d_in[20];
    const float* b_fg   = (const float*)d_in[21];
    const float* W_gate = (const float*)d_in[22];
    const float* b_gate = (const float*)d_in[23];
    const float* W_out  = (const float*)d_in[24];
    const float* b_out  = (const float*)d_in[25];
    float* out = (float*)d_out;

    float *qpi, *qps, *ipb, *spb, *ictx, *sctx, *cat, *gcat, *part;
    float *h_r, *img_r, *sem_r;
    float *Wcif_r, *Wcsf_r, *Wcii_r, *Wcsn_r, *Wfg_r, *Wig_r, *Wsg_r, *Wgate_r, *Wout_r;
    cudaGetSymbolAddress((void**)&qpi,  g_qproj_img);
    cudaGetSymbolAddress((void**)&qps,  g_qproj_sem);
    cudaGetSymbolAddress((void**)&ipb,  g_ip);
    cudaGetSymbolAddress((void**)&spb,  g_sp);
    cudaGetSymbolAddress((void**)&ictx, g_img_ctx);
    cudaGetSymbolAddress((void**)&sctx, g_sem_ctx);
    cudaGetSymbolAddress((void**)&cat,  g_cat);
    cudaGetSymbolAddress((void**)&gcat, g_gcat);
    cudaGetSymbolAddress((void**)&part, g_part);
    cudaGetSymbolAddress((void**)&h_r,    g_h_r);
    cudaGetSymbolAddress((void**)&img_r,  g_img_r);
    cudaGetSymbolAddress((void**)&sem_r,  g_sem_r);
    cudaGetSymbolAddress((void**)&Wcif_r, g_Wcif_r);
    cudaGetSymbolAddress((void**)&Wcsf_r, g_Wcsf_r);
    cudaGetSymbolAddress((void**)&Wcii_r, g_Wcii_r);
    cudaGetSymbolAddress((void**)&Wcsn_r, g_Wcsn_r);
    cudaGetSymbolAddress((void**)&Wfg_r,  g_Wfg_r);
    cudaGetSymbolAddress((void**)&Wig_r,  g_Wig_r);
    cudaGetSymbolAddress((void**)&Wsg_r,  g_Wsg_r);
    cudaGetSymbolAddress((void**)&Wgate_r,g_Wgate_r);
    cudaGetSymbolAddress((void**)&Wout_r, g_Wout_r);

    static bool attr_set = false;
    if (!attr_set) {
        cudaFuncSetAttribute(mma_gemm, cudaFuncAttributeMaxDynamicSharedMemorySize, GEMM_SMEM);
        cudaFuncSetAttribute(att_catf, cudaFuncAttributeMaxDynamicSharedMemorySize, GEMM_SMEM);
        attr_set = true;
    }

    const int MI = MROWS_I * PP;           // 147456
    const int MG = ROWS * CATD;            // 3145728
    const int MO = ROWS * OUTD;            // 2097152

    // 1: prep — tf32 rounding (early tensors) + qproj
    {
        PrepArgs P{};
        P.src[0] = h;      P.dst[0] = h_r;    P.n4[0] = ROWS*IN_D/4;
        P.src[1] = img;    P.dst[1] = img_r;  P.n4[1] = MROWS_I*IMG_D/4;
        P.src[2] = sem;    P.dst[2] = sem_r;  P.n4[2] = MROWS_S*SEM_D/4;
        P.src[3] = W_cif;  P.dst[3] = Wcif_r; P.n4[3] = IN_D*PP/4;
        P.src[4] = W_csf;  P.dst[4] = Wcsf_r; P.n4[4] = IN_D*PP/4;
        P.src[5] = W_cii;  P.dst[5] = Wcii_r; P.n4[5] = IMG_D*PP/4;
        P.src[6] = W_csn;  P.dst[6] = Wcsn_r; P.n4[6] = SEM_D*PP/4;
        P.src[7] = W_fg;   P.dst[7] = Wfg_r;  P.n4[7] = IN_D*PP/4;
        P.que = que;
        P.W1 = W_cif + (size_t)IN_D * PP; P.b1 = b_cif; P.o1 = qpi;
        P.W2 = W_csf + (size_t)IN_D * PP; P.b2 = b_csf; P.o2 = qps;
        prep_kernel<<<1056, 256>>>(P);
    }
    // 2: BIG1 — np partials [0,4M1), ip partials [4M1,..), sp
    {
        TaskList L{};
        for (int c = 0; c < 2; c++) {
            L.t[c]     = { h_r + 512*c, Wcif_r + (size_t)512*c*PP, nullptr, nullptr,
                           part + (size_t)c*M1, IN_D, PP, 0, PP, ROWS, 512, 3, 0 };
            L.t[2 + c] = { h_r + 512*c, Wcsf_r + (size_t)512*c*PP, nullptr, nullptr,
                           part + (size_t)(2 + c)*M1, IN_D, PP, 0, PP, ROWS, 512, 3, 0 };
        }
        for (int c = 0; c < 4; c++)
            L.t[4 + c] = { img_r + 512*c, Wcii_r + (size_t)512*c*PP, nullptr, nullptr,
                           part + (size_t)4*M1 + (size_t)c*MI, IMG_D, PP, 0, PP, MROWS_I, 512, 3, 0 };
        L.t[8] = { sem_r, Wcsn_r, nullptr, nullptr,
                   part + (size_t)4*M1 + (size_t)4*MI, SEM_D, PP, 0, PP, MROWS_S, 512, 3, 0 };
        mma_gemm<<<dim3(4, 16, 9), 256, GEMM_SMEM>>>(L);
    }
    // 3: RED1 — ip (sum4 + bias), sp (bias)
    {
        RList L{};
        L.t[0] = { part + (size_t)4*M1,        4, MI, b_cii, nullptr, 0, ipb, PP, MROWS_I, PP, 0, 0 };
        L.t[1] = { part + (size_t)4*M1 + 4*MI, 1, 0,  b_csn, nullptr, 0, spb, PP, MROWS_S, PP, 0, 0 };
        reduce_k<<<dim3(256, 2), 256>>>(L);
    }
    // 4: fat kernel — cat-f GEMM + attentions + late weight cvts  <-- profiled slot
    {
        AttArgs A{};
        A.np0i = part;                A.np1i = part + (size_t)M1;   A.qpi = qpi;
        A.ipb = ipb; A.img = img; A.w_ia = w_ia; A.ictx = ictx;
        A.np0s = part + (size_t)2*M1; A.np1s = part + (size_t)3*M1; A.qps = qps;
        A.spb = spb; A.sem = sem; A.w_sa = w_sa; A.sctx = sctx;
        A.csrc[0] = W_ig;   A.cdst[0] = Wig_r;   A.cn4[0] = IMG_D*PP/4;
        A.csrc[1] = W_sg;   A.cdst[1] = Wsg_r;   A.cn4[1] = SEM_D*PP/4;
        A.csrc[2] = W_gate; A.cdst[2] = Wgate_r; A.cn4[2] = CATD*CATD/4;
        A.csrc[3] = W_out;  A.cdst[3] = Wout_r;  A.cn4[3] = CATD*OUTD/4;
        TaskDesc g0 = { h_r,       Wfg_r,                  nullptr, nullptr,
                        part + (size_t)5*M1, IN_D, PP, 0, PP, ROWS, 512, 3, 0 };
        TaskDesc g1 = { h_r + 512, Wfg_r + (size_t)512*PP, nullptr, nullptr,
                        part + (size_t)6*M1, IN_D, PP, 0, PP, ROWS, 512, 3, 0 };
        att_catf<<<768, 256, GEMM_SMEM>>>(A, g0, g1);
    }
    // 5: BIG2rest — cat-i (4 chunks at 7M1..), cat-s (at 11M1)
    {
        TaskList L{};
        for (int c = 0; c < 4; c++)
            L.t[c] = { ictx + 512*c, Wig_r + (size_t)512*c*PP, nullptr, nullptr,
                       part + (size_t)(7 + c)*M1, IMG_D, PP, 0, PP, ROWS, 512, 3, 0 };
        L.t[4] = { sctx, Wsg_r, nullptr, nullptr,
                   part + (size_t)11*M1, SEM_D, PP, 0, PP, ROWS, 512, 3, 0 };
        mma_gemm<<<dim3(4, 16, 5), 256, GEMM_SMEM>>>(L);
    }
    // 6: RED2 — assemble cat (bias + tf32-round)
    {
        RList L{};
        L.t[0] = { part + (size_t)5*M1,  2, M1, b_fg, nullptr, 0, cat,        CATD, ROWS, PP, 0, 1 };
        L.t[1] = { part + (size_t)7*M1,  4, M1, b_ig, nullptr, 0, cat + PP,   CATD, ROWS, PP, 0, 1 };
        L.t[2] = { part + (size_t)11*M1, 1, 0,  b_sg, nullptr, 0, cat + 2*PP, CATD, ROWS, PP, 0, 1 };
        reduce_k<<<dim3(256, 3), 256>>>(L);
    }
    // 7: BIG3 — gate in 2 K-chunks of 768 (384 CTAs)
    {
        TaskList L{};
        for (int c = 0; c < 2; c++)
            L.t[c] = { cat + 768*c, Wgate_r + (size_t)768*c*CATD, nullptr, nullptr,
                       part + (size_t)c*MG, CATD, CATD, 0, CATD, ROWS, 768, 3, 0 };
        mma_gemm<<<dim3(12, 16, 2), 256, GEMM_SMEM>>>(L);
    }
    // 8: REDG — gcat = tf32( sigmoid(sum2 + b_gate) * cat )
    {
        RList L{};
        L.t[0] = { part, 2, MG, b_gate, cat, CATD, gcat, CATD, ROWS, CATD, 2, 1 };
        reduce_k<<<dim3(256, 1), 256>>>(L);
    }
    // 9: BIG4 — out in 2 K-chunks of 768
    {
        TaskList L{};
        for (int c = 0; c < 2; c++)
            L.t[c] = { gcat + 768*c, Wout_r + (size_t)768*c*OUTD, nullptr, nullptr,
                       part + (size_t)(6 + c)*M1 * 2, CATD, OUTD, 0, OUTD, ROWS, 768, 3, 0 };
        // note: 6*2*M1 = 12M1 exceeds scratch; use distinct safe region below instead
        L.t[0].C = part + (size_t)8*M1;      // 8M1..10M1
        L.t[1].C = part + (size_t)10*M1;     // 10M1..12M1
        mma_gemm<<<dim3(8, 16, 2), 256, GEMM_SMEM>>>(L);
    }
    // 10: RED3 — out = sum2 + bias
    {
        RList L{};
        L.t[0] = { part + (size_t)8*M1, 2, (int)((size_t)2*M1), b_out, nullptr, 0, out, OUTD, ROWS, OUTD, 0, 0 };
        reduce_k<<<dim3(256, 1), 256>>>(L);
    }
}

// round 15
// speedup vs baseline: 1.1194x; 1.1194x over previous
#include <cuda_runtime.h>
#include <cstdint>

// ---------------- problem dims ----------------
#define BB 8
#define NN 256
#define NI 36
#define SS 64
#define IN_D 1024
#define QUE_D 1024
#define IMG_D 2048
#define SEM_D 512
#define PP 512
#define CATD 1536
#define OUTD 1024
#define ROWS (BB*NN)
#define MROWS_I (BB*NI)   // 288
#define MROWS_S (BB*SS)   // 512
#define M1 (ROWS*PP)      // 1048576

// ---------------- scratch ----------------
__device__ float g_qproj_img[BB*PP];
__device__ float g_qproj_sem[BB*PP];
__device__ float g_ip[MROWS_I*PP];
__device__ float g_sp[MROWS_S*PP];
__device__ float g_img_ctx[ROWS*IMG_D];
__device__ float g_sem_ctx[ROWS*SEM_D];
__device__ float g_cat[ROWS*CATD];
__device__ float g_gcat[ROWS*CATD];
__device__ float g_part[12*1024*1024];    // 48MB partial-sum scratch
// tf32-pre-rounded copies
__device__ float g_h_r[ROWS*IN_D];
__device__ float g_img_r[MROWS_I*IMG_D];
__device__ float g_sem_r[MROWS_S*SEM_D];
__device__ float g_Wcif_r[IN_D*PP];
__device__ float g_Wcsf_r[IN_D*PP];
__device__ float g_Wcii_r[IMG_D*PP];
__device__ float g_Wcsn_r[SEM_D*PP];
__device__ float g_Wfg_r[IN_D*PP];
__device__ float g_Wig_r[IMG_D*PP];
__device__ float g_Wsg_r[SEM_D*PP];
__device__ float g_Wgate_r[CATD*CATD];
__device__ float g_Wout_r[CATD*OUTD];

// ---------------- helpers ----------------
__device__ __forceinline__ float tanh_fast(float x) {
    float y; asm("tanh.approx.f32 %0, %1;" : "=f"(y) : "f"(x)); return y;
}
__device__ __forceinline__ float sigmoid_fast(float x) {
    return 1.0f / (1.0f + __expf(-x));
}
__device__ __forceinline__ float f2tf_f(float x) {
    uint32_t r; asm("cvt.rna.tf32.f32 %0, %1;" : "=r"(r) : "f"(x));
    return __uint_as_float(r);
}
__device__ __forceinline__ void mma8(float* c, const uint32_t* a, uint32_t b0, uint32_t b1) {
    asm("mma.sync.aligned.m16n8k8.row.col.f32.tf32.tf32.f32 "
        "{%0,%1,%2,%3}, {%4,%5,%6,%7}, {%8,%9}, {%0,%1,%2,%3};"
        : "+f"(c[0]), "+f"(c[1]), "+f"(c[2]), "+f"(c[3])
        : "r"(a[0]), "r"(a[1]), "r"(a[2]), "r"(a[3]), "r"(b0), "r"(b1));
}
__device__ __forceinline__ uint32_t smem_u32(const void* p) {
    uint32_t a;
    asm("{ .reg .u64 t; cvta.to.shared.u64 t, %1; cvt.u32.u64 %0, t; }" : "=r"(a) : "l"(p));
    return a;
}
#define CP_ASYNC16(dst, src) \
    asm volatile("cp.async.cg.shared.global [%0], [%1], 16;" :: "r"(dst), "l"(src))
#define CP_COMMIT() asm volatile("cp.async.commit_group;" ::: "memory")
#define CP_WAIT1()  asm volatile("cp.async.wait_group 1;" ::: "memory")

// ---------------- GEMM core: CTA 128x128, 8 warps of 64x32 ----------------
struct TaskDesc {
    const float* A; const float* W; const float* bias; const float* extra;
    float* C; int lda, ldw, lde, ldc, M, K, mode, rnd;
};
struct TaskList { TaskDesc t[9]; };

#define STG_FLOATS 8192          // 32KB/stage
#define GEMM_SMEM (3 * STG_FLOATS * 4)

__global__ __launch_bounds__(256, 2)
void mma_gemm(TaskList TL) {
    extern __shared__ float sm[];
    const TaskDesc T = TL.t[blockIdx.z];
    const int m0 = blockIdx.y * 128;
    if (m0 >= T.M) return;
    const int n0 = blockIdx.x * 128;
    const uint32_t smb = smem_u32(sm);

    const int tid = threadIdx.x;
    const int lane = tid & 31;
    const int wid = tid >> 5;
    const int wr = wid >> 2;
    const int wc = wid & 3;

    const int arow = tid >> 3;
    const int ac   = tid & 7;
    const int bk   = tid >> 3;
    const int bc0  = tid & 7;

    uint32_t adst[4], bdst[4];
#pragma unroll
    for (int s = 0; s < 4; s++) {
        int row = arow + 32 * s;
        adst[s] = (uint32_t)(row * 128 + ((ac ^ (row & 7)) << 4));
    }
#pragma unroll
    for (int j = 0; j < 4; j++) {
        int c = bc0 + 8 * j;
        bdst[j] = (uint32_t)(16384 + bk * 512 + ((c ^ ((bk & 3) << 1)) << 4));
    }
    const float* Asrc[4];
#pragma unroll
    for (int s = 0; s < 4; s++) {
        int r = m0 + arow + 32 * s;
        if (r >= T.M) r = T.M - 1;
        Asrc[s] = T.A + (size_t)r * T.lda + ac * 4;
    }
    const float* Bsrc = T.W + (size_t)bk * T.ldw + n0 + bc0 * 4;

    const int S = T.K >> 5;

    auto issue_stage = [&](int i) {
        uint32_t base = smb + (uint32_t)(i % 3) * (STG_FLOATS * 4);
        int k0 = i << 5;
#pragma unroll
        for (int s = 0; s < 4; s++) CP_ASYNC16(base + adst[s], Asrc[s] + k0);
        const float* wsrc = Bsrc + (size_t)k0 * T.ldw;
#pragma unroll
        for (int j = 0; j < 4; j++) CP_ASYNC16(base + bdst[j], wsrc + 8 * j * 4);
    };

    float acc[4][4][4];
#pragma unroll
    for (int i = 0; i < 4; i++)
#pragma unroll
        for (int t = 0; t < 4; t++)
#pragma unroll
            for (int r = 0; r < 4; r++) acc[i][t][r] = 0.0f;

    issue_stage(0); CP_COMMIT();
    if (S > 1) issue_stage(1);
    CP_COMMIT();

    const int lrow = lane >> 2;
    const int lk   = lane & 3;

    for (int i = 0; i < S; i++) {
        CP_WAIT1();
        __syncthreads();

        const float* base = sm + (size_t)(i % 3) * STG_FLOATS;
#pragma unroll
        for (int kk = 0; kk < 4; kk++) {
            uint32_t a[4][4], b[4][2];
#pragma unroll
            for (int ii = 0; ii < 4; ii++) {
                int mt = wr * 4 + ii;
#pragma unroll
                for (int r = 0; r < 4; r++) {
                    int row = mt * 16 + lrow + 8 * (r & 1);
                    int k = kk * 8 + lk + 4 * (r >> 1);
                    a[ii][r] = __float_as_uint(
                        base[row * 32 + (((k >> 2) ^ (row & 7)) << 2) + (k & 3)]);
                }
            }
#pragma unroll
            for (int t = 0; t < 4; t++) {
                int nt = wc * 4 + t;
#pragma unroll
                for (int r = 0; r < 2; r++) {
                    int k = kk * 8 + lk + 4 * r;
                    int n = nt * 8 + lrow;
                    b[t][r] = __float_as_uint(
                        base[4096 + k * 128 + (((n >> 2) ^ ((k & 3) << 1)) << 2) + (n & 3)]);
                }
            }
#pragma unroll
            for (int ii = 0; ii < 4; ii++)
#pragma unroll
                for (int t = 0; t < 4; t++)
                    mma8(acc[ii][t], a[ii], b[t][0], b[t][1]);
        }

        if (i + 2 < S) issue_stage(i + 2);
        CP_COMMIT();
    }

#pragma unroll
    for (int i = 0; i < 4; i++) {
        int rbase = m0 + wr * 64 + i * 16 + lrow;
#pragma unroll
        for (int t = 0; t < 4; t++) {
            int cb = n0 + wc * 32 + t * 8 + 2 * lk;
#pragma unroll
            for (int hh = 0; hh < 2; hh++) {
                int r = rbase + 8 * hh;
                if (r >= T.M) continue;
                float c0 = acc[i][t][2 * hh], c1 = acc[i][t][2 * hh + 1];
                float2 v;
                if (T.mode == 3) {
                    v = make_float2(c0, c1);
                } else if (T.mode == 0) {
                    float2 bs = *(const float2*)(T.bias + cb);
                    v = make_float2(c0 + bs.x, c1 + bs.y);
                } else if (T.mode == 1) {
                    float2 ev = *(const float2*)(T.extra + (size_t)(r >> 8) * T.lde + cb);
                    v = make_float2(c0 + ev.x, c1 + ev.y);
                } else {
                    float2 bs = *(const float2*)(T.bias + cb);
                    float2 ev = *(const float2*)(T.extra + (size_t)r * T.lde + cb);
                    v = make_float2(sigmoid_fast(c0 + bs.x) * ev.x,
                                    sigmoid_fast(c1 + bs.y) * ev.y);
                }
                if (T.rnd) { v.x = f2tf_f(v.x); v.y = f2tf_f(v.y); }
                *(float2*)(T.C + (size_t)r * T.ldc + cb) = v;
            }
        }
    }
}

// ---------------- partial-sum reduce + epilogue ----------------
struct RTask {
    const float* p; int nparts; int pstride;
    const float* bias; const float* extra; int lde;
    float* o; int ldo; int M, N, mode, rnd;
};
struct RList { RTask t[4]; };
__global__ __launch_bounds__(256)
void reduce_k(RList L) {
    RTask R = L.t[blockIdx.y];
    const int n4 = R.N >> 2;
    const int total = R.M * n4;
    for (int i = blockIdx.x * 256 + threadIdx.x; i < total; i += gridDim.x * 256) {
        int r = i / n4, c4 = i - r * n4;
        const float4* pp = (const float4*)R.p + (size_t)r * n4 + c4;
        float4 s = *pp;
        for (int q = 1; q < R.nparts; q++) {
            float4 v = *(const float4*)((const float*)pp + (size_t)q * R.pstride);
            s.x += v.x; s.y += v.y; s.z += v.z; s.w += v.w;
        }
        if (R.mode == 0) {
            float4 bv = *(const float4*)(R.bias + c4 * 4);
            s.x += bv.x; s.y += bv.y; s.z += bv.z; s.w += bv.w;
        } else if (R.mode == 1) {
            float4 ev = *(const float4*)(R.extra + (size_t)(r >> 8) * R.lde + c4 * 4);
            s.x += ev.x; s.y += ev.y; s.z += ev.z; s.w += ev.w;
        } else {
            float4 bv = *(const float4*)(R.bias + c4 * 4);
            float4 ev = *(const float4*)(R.extra + (size_t)r * R.lde + c4 * 4);
            s.x = sigmoid_fast(s.x + bv.x) * ev.x;
            s.y = sigmoid_fast(s.y + bv.y) * ev.y;
            s.z = sigmoid_fast(s.z + bv.z) * ev.z;
            s.w = sigmoid_fast(s.w + bv.w) * ev.w;
        }
        if (R.rnd) { s.x = f2tf_f(s.x); s.y = f2tf_f(s.y); s.z = f2tf_f(s.z); s.w = f2tf_f(s.w); }
        *(float4*)(R.o + (size_t)r * R.ldo + c4 * 4) = s;
    }
}

// ---------------- prep: tf32 rounding (12 tensors) + qproj ----------------
struct PrepArgs {
    const float* src[12]; float* dst[12]; int n4[12];
    const float* que;
    const float* W1; const float* b1; float* o1;
    const float* W2; const float* b2; float* o2;
};
__global__ __launch_bounds__(256)
void prep_kernel(PrepArgs P) {
    const int g = blockIdx.x;
    const int tid = threadIdx.x;
    if (g < 1536) {
        int z = g >> 7;
        const float4* s = (const float4*)P.src[z];
        float4* d = (float4*)P.dst[z];
        int n4 = P.n4[z];
        for (int i = (g & 127) * 256 + tid; i < n4; i += 128 * 256) {
            float4 v = s[i];
            v.x = f2tf_f(v.x); v.y = f2tf_f(v.y); v.z = f2tf_f(v.z); v.w = f2tf_f(v.w);
            d[i] = v;
        }
    } else {
        int g2 = g - 1536;
        int z  = g2 >> 4;
        int b  = (g2 >> 1) & 7;
        int j  = (g2 & 1) * 256 + tid;
        const float* Wsub = z ? P.W2 : P.W1;
        const float* bias = z ? P.b2 : P.b1;
        float* out = z ? P.o2 : P.o1;
        const float* q = P.que + b * QUE_D;
        float a0 = 0.f, a1 = 0.f, a2 = 0.f, a3 = 0.f;
#pragma unroll 2
        for (int k = 0; k < QUE_D; k += 4) {
            a0 = fmaf(q[k],     Wsub[(size_t)k * PP + j],       a0);
            a1 = fmaf(q[k + 1], Wsub[(size_t)(k + 1) * PP + j], a1);
            a2 = fmaf(q[k + 2], Wsub[(size_t)(k + 2) * PP + j], a2);
            a3 = fmaf(q[k + 3], Wsub[(size_t)(k + 3) * PP + j], a3);
        }
        out[b * PP + j] = bias[j] + ((a0 + a1) + (a2 + a3));
    }
}

// ---------------- attention body (np from 2 partials + qproj; ctx tf32-rounded) ----------------
template <int KN, int D, int RSPLIT>
__device__ __forceinline__ void att_body(int g,
        const float* __restrict__ np0, const float* __restrict__ np1,
        const float* __restrict__ qp,
        const float* __restrict__ kp,
        const float* __restrict__ kv, const float* __restrict__ w,
        float* __restrict__ ctx) {
    __shared__ __align__(16) float s_w[PP];
    __shared__ float s_logit[8][64];
    __shared__ float s_att[8][64];

    const int b = g >> 5;
    const int r0 = (g & 31) * 8;
    const int tid = threadIdx.x;
    const int wid = tid >> 5, lane = tid & 31;

    for (int i = tid; i < PP; i += 256) s_w[i] = w[i];

    const int row = b * NN + r0 + wid;
    float4 npv[4];
    const float4* nr0 = (const float4*)(np0 + (size_t)row * PP);
    const float4* nr1 = (const float4*)(np1 + (size_t)row * PP);
    const float4* qr  = (const float4*)(qp + (size_t)b * PP);
#pragma unroll
    for (int i = 0; i < 4; i++) {
        float4 x = nr0[lane + 32 * i];
        float4 y = nr1[lane + 32 * i];
        float4 q = qr[lane + 32 * i];
        npv[i] = make_float4((x.x + y.x) + q.x, (x.y + y.y) + q.y,
                             (x.z + y.z) + q.z, (x.w + y.w) + q.w);
    }
    __syncthreads();

    for (int k = 0; k < KN; k++) {
        const float4* kr = (const float4*)(kp + (size_t)(b * KN + k) * PP);
        float a0 = 0.f, a1 = 0.f, a2 = 0.f, a3 = 0.f;
        {
            float4 k0 = kr[lane],       w0 = ((const float4*)s_w)[lane];
            float4 k1 = kr[lane + 32],  w1 = ((const float4*)s_w)[lane + 32];
            float4 k2 = kr[lane + 64],  w2 = ((const float4*)s_w)[lane + 64];
            float4 k3 = kr[lane + 96],  w3 = ((const float4*)s_w)[lane + 96];
            a0 = fmaf(tanh_fast(npv[0].x + k0.x), w0.x, a0);
            a1 = fmaf(tanh_fast(npv[0].y + k0.y), w0.y, a1);
            a2 = fmaf(tanh_fast(npv[0].z + k0.z), w0.z, a2);
            a3 = fmaf(tanh_fast(npv[0].w + k0.w), w0.w, a3);
            a0 = fmaf(tanh_fast(npv[1].x + k1.x), w1.x, a0);
            a1 = fmaf(tanh_fast(npv[1].y + k1.y), w1.y, a1);
            a2 = fmaf(tanh_fast(npv[1].z + k1.z), w1.z, a2);
            a3 = fmaf(tanh_fast(npv[1].w + k1.w), w1.w, a3);
            a0 = fmaf(tanh_fast(npv[2].x + k2.x), w2.x, a0);
            a1 = fmaf(tanh_fast(npv[2].y + k2.y), w2.y, a1);
            a2 = fmaf(tanh_fast(npv[2].z + k2.z), w2.z, a2);
            a3 = fmaf(tanh_fast(npv[2].w + k2.w), w2.w, a3);
            a0 = fmaf(tanh_fast(npv[3].x + k3.x), w3.x, a0);
            a1 = fmaf(tanh_fast(npv[3].y + k3.y), w3.y, a1);
            a2 = fmaf(tanh_fast(npv[3].z + k3.z), w3.z, a2);
            a3 = fmaf(tanh_fast(npv[3].w + k3.w), w3.w, a3);
        }
        float acc = (a0 + a1) + (a2 + a3);
#pragma unroll
        for (int o = 16; o > 0; o >>= 1) acc += __shfl_xor_sync(0xffffffff, acc, o);
        if (lane == 0) s_logit[wid][k] = acc;
    }
    __syncwarp();

    {
        float l0 = (lane < KN) ? s_logit[wid][lane] : -1e30f;
        float l1 = (lane + 32 < KN) ? s_logit[wid][lane + 32] : -1e30f;
        float m = fmaxf(l0, l1);
#pragma unroll
        for (int o = 16; o > 0; o >>= 1) m = fmaxf(m, __shfl_xor_sync(0xffffffff, m, o));
        float e0 = (lane < KN) ? __expf(l0 - m) : 0.0f;
        float e1 = (lane + 32 < KN) ? __expf(l1 - m) : 0.0f;
        float sum = e0 + e1;
#pragma unroll
        for (int o = 16; o > 0; o >>= 1) sum += __shfl_xor_sync(0xffffffff, sum, o);
        float inv = 1.0f / sum;
        s_att[wid][lane] = e0 * inv;
        if (lane + 32 < 64) s_att[wid][lane + 32] = e1 * inv;
    }
    __syncthreads();

    const float4* kvb = (const float4*)(kv + (size_t)b * KN * D);
    if (RSPLIT) {
        const int half = tid >> 7;
        const int d4 = tid & 127;
        float4 a[4];
#pragma unroll
        for (int r = 0; r < 4; r++) a[r] = make_float4(0.f, 0.f, 0.f, 0.f);
        for (int k = 0; k < KN; k++) {
            float4 v = kvb[(size_t)k * (D / 4) + d4];
#pragma unroll
            for (int r = 0; r < 4; r++) {
                float at = s_att[half * 4 + r][k];
                a[r].x = fmaf(at, v.x, a[r].x);
                a[r].y = fmaf(at, v.y, a[r].y);
                a[r].z = fmaf(at, v.z, a[r].z);
                a[r].w = fmaf(at, v.w, a[r].w);
            }
        }
#pragma unroll
        for (int r = 0; r < 4; r++) {
            float4 o;
            o.x = f2tf_f(a[r].x); o.y = f2tf_f(a[r].y);
            o.z = f2tf_f(a[r].z); o.w = f2tf_f(a[r].w);
            *(float4*)(ctx + (size_t)(b * NN + r0 + half * 4 + r) * D + d4 * 4) = o;
        }
    } else {
        for (int d4 = tid; d4 < D / 4; d4 += 256) {
            float4 a[8];
#pragma unroll
            for (int r = 0; r < 8; r++) a[r] = make_float4(0.f, 0.f, 0.f, 0.f);
            for (int k = 0; k < KN; k++) {
                float4 v = kvb[(size_t)k * (D / 4) + d4];
#pragma unroll
                for (int r = 0; r < 8; r++) {
                    float at = s_att[r][k];
                    a[r].x = fmaf(at, v.x, a[r].x);
                    a[r].y = fmaf(at, v.y, a[r].y);
                    a[r].z = fmaf(at, v.z, a[r].z);
                    a[r].w = fmaf(at, v.w, a[r].w);
                }
            }
#pragma unroll
            for (int r = 0; r < 8; r++) {
                float4 o;
                o.x = f2tf_f(a[r].x); o.y = f2tf_f(a[r].y);
                o.z = f2tf_f(a[r].z); o.w = f2tf_f(a[r].w);
                *(float4*)(ctx + (size_t)(b * NN + r0 + r) * D + d4 * 4) = o;
            }
        }
    }
}

// standalone attention: occupancy 4 CTAs/SM (regs<=64, 6KB smem), 512 blocks < 1 wave
struct AttArgs {
    const float* np0i; const float* np1i; const float* qpi;
    const float* ipb; const float* img; const float* w_ia; float* ictx;
    const float* np0s; const float* np1s; const float* qps;
    const float* spb; const float* sem; const float* w_sa; float* sctx;
};
__global__ __launch_bounds__(256, 4)
void att_both(AttArgs A) {
    const int bid = blockIdx.x;
    if (bid < 256)
        att_body<NI, IMG_D, 0>(bid, A.np0i, A.np1i, A.qpi, A.ipb, A.img, A.w_ia, A.ictx);
    else
        att_body<SS, SEM_D, 1>(bid - 256, A.np0s, A.np1s, A.qps, A.spb, A.sem, A.w_sa, A.sctx);
}

// ---------------- launch ----------------
extern "C" void kernel_launch(void* const* d_in, const int* in_sizes, int n_in,
                              void* d_out, int out_size) {
    const float* h      = (const float*)d_in[0];
    const float* img    = (const float*)d_in[1];
    const float* sem    = (const float*)d_in[2];
    const float* que    = (const float*)d_in[3];
    const float* W_cif  = (const float*)d_in[4];
    const float* b_cif  = (const float*)d_in[5];
    const float* W_cii  = (const float*)d_in[6];
    const float* b_cii  = (const float*)d_in[7];
    const float* w_ia   = (const float*)d_in[8];
    const float* W_csf  = (const float*)d_in[10];
    const float* b_csf  = (const float*)d_in[11];
    const float* W_csn  = (const float*)d_in[12];
    const float* b_csn  = (const float*)d_in[13];
    const float* w_sa   = (const float*)d_in[14];
    const float* W_ig   = (const float*)d_in[16];
    const float* b_ig   = (const float*)d_in[17];
    const float* W_sg   = (const float*)d_in[18];
    const float* b_sg   = (const float*)d_in[19];
    const float* W_fg   = (const float*)d_in[20];
    const float* b_fg   = (const float*)d_in[21];
    const float* W_gate = (const float*)d_in[22];
    const float* b_gate = (const float*)d_in[23];
    const float* W_out  = (const float*)d_in[24];
    const float* b_out  = (const float*)d_in[25];
    float* out = (float*)d_out;

    float *qpi, *qps, *ipb, *spb, *ictx, *sctx, *cat, *gcat, *part;
    float *h_r, *img_r, *sem_r;
    float *Wcif_r, *Wcsf_r, *Wcii_r, *Wcsn_r, *Wfg_r, *Wig_r, *Wsg_r, *Wgate_r, *Wout_r;
    cudaGetSymbolAddress((void**)&qpi,  g_qproj_img);
    cudaGetSymbolAddress((void**)&qps,  g_qproj_sem);
    cudaGetSymbolAddress((void**)&ipb,  g_ip);
    cudaGetSymbolAddress((void**)&spb,  g_sp);
    cudaGetSymbolAddress((void**)&ictx, g_img_ctx);
    cudaGetSymbolAddress((void**)&sctx, g_sem_ctx);
    cudaGetSymbolAddress((void**)&cat,  g_cat);
    cudaGetSymbolAddress((void**)&gcat, g_gcat);
    cudaGetSymbolAddress((void**)&part, g_part);
    cudaGetSymbolAddress((void**)&h_r,    g_h_r);
    cudaGetSymbolAddress((void**)&img_r,  g_img_r);
    cudaGetSymbolAddress((void**)&sem_r,  g_sem_r);
    cudaGetSymbolAddress((void**)&Wcif_r, g_Wcif_r);
    cudaGetSymbolAddress((void**)&Wcsf_r, g_Wcsf_r);
    cudaGetSymbolAddress((void**)&Wcii_r, g_Wcii_r);
    cudaGetSymbolAddress((void**)&Wcsn_r, g_Wcsn_r);
    cudaGetSymbolAddress((void**)&Wfg_r,  g_Wfg_r);
    cudaGetSymbolAddress((void**)&Wig_r,  g_Wig_r);
    cudaGetSymbolAddress((void**)&Wsg_r,  g_Wsg_r);
    cudaGetSymbolAddress((void**)&Wgate_r,g_Wgate_r);
    cudaGetSymbolAddress((void**)&Wout_r, g_Wout_r);

    static bool attr_set = false;
    if (!attr_set) {
        cudaFuncSetAttribute(mma_gemm, cudaFuncAttributeMaxDynamicSharedMemorySize, GEMM_SMEM);
        attr_set = true;
    }

    const int MI = MROWS_I * PP;           // 147456
    const int MG = ROWS * CATD;            // 3145728
    const int MO = ROWS * OUTD;            // 2097152

    // 1: prep — tf32 rounding (12 tensors) + qproj
    {
        PrepArgs P{};
        P.src[0] = h;      P.dst[0] = h_r;    P.n4[0] = ROWS*IN_D/4;
        P.src[1] = img;    P.dst[1] = img_r;  P.n4[1] = MROWS_I*IMG_D/4;
        P.src[2] = sem;    P.dst[2] = sem_r;  P.n4[2] = MROWS_S*SEM_D/4;
        P.src[3] = W_cif;  P.dst[3] = Wcif_r; P.n4[3] = IN_D*PP/4;
        P.src[4] = W_csf;  P.dst[4] = Wcsf_r; P.n4[4] = IN_D*PP/4;
        P.src[5] = W_cii;  P.dst[5] = Wcii_r; P.n4[5] = IMG_D*PP/4;
        P.src[6] = W_csn;  P.dst[6] = Wcsn_r; P.n4[6] = SEM_D*PP/4;
        P.src[7] = W_fg;   P.dst[7] = Wfg_r;  P.n4[7] = IN_D*PP/4;
        P.src[8] = W_ig;   P.dst[8] = Wig_r;  P.n4[8] = IMG_D*PP/4;
        P.src[9] = W_sg;   P.dst[9] = Wsg_r;  P.n4[9] = SEM_D*PP/4;
        P.src[10]= W_gate; P.dst[10]= Wgate_r;P.n4[10]= CATD*CATD/4;
        P.src[11]= W_out;  P.dst[11]= Wout_r; P.n4[11]= CATD*OUTD/4;
        P.que = que;
        P.W1 = W_cif + (size_t)IN_D * PP; P.b1 = b_cif; P.o1 = qpi;
        P.W2 = W_csf + (size_t)IN_D * PP; P.b2 = b_csf; P.o2 = qps;
        prep_kernel<<<1568, 256>>>(P);
    }
    // 2: BIG1 — np partials [0,4M1), ip partials [4M1,..), sp
    {
        TaskList L{};
        for (int c = 0; c < 2; c++) {
            L.t[c]     = { h_r + 512*c, Wcif_r + (size_t)512*c*PP, nullptr, nullptr,
                           part + (size_t)c*M1, IN_D, PP, 0, PP, ROWS, 512, 3, 0 };
            L.t[2 + c] = { h_r + 512*c, Wcsf_r + (size_t)512*c*PP, nullptr, nullptr,
                           part + (size_t)(2 + c)*M1, IN_D, PP, 0, PP, ROWS, 512, 3, 0 };
        }
        for (int c = 0; c < 4; c++)
            L.t[4 + c] = { img_r + 512*c, Wcii_r + (size_t)512*c*PP, nullptr, nullptr,
                           part + (size_t)4*M1 + (size_t)c*MI, IMG_D, PP, 0, PP, MROWS_I, 512, 3, 0 };
        L.t[8] = { sem_r, Wcsn_r, nullptr, nullptr,
                   part + (size_t)4*M1 + (size_t)4*MI, SEM_D, PP, 0, PP, MROWS_S, 512, 3, 0 };
        mma_gemm<<<dim3(4, 16, 9), 256, GEMM_SMEM>>>(L);
    }
    // 3: RED1 — ip (sum4 + bias), sp (bias)
    {
        RList L{};
        L.t[0] = { part + (size_t)4*M1,        4, MI, b_cii, nullptr, 0, ipb, PP, MROWS_I, PP, 0, 0 };
        L.t[1] = { part + (size_t)4*M1 + 4*MI, 1, 0,  b_csn, nullptr, 0, spb, PP, MROWS_S, PP, 0, 0 };
        reduce_k<<<dim3(256, 2), 256>>>(L);
    }
    // 4: attention (standalone, 4 CTAs/SM)  <-- profiled slot
    {
        AttArgs A{ part, part + (size_t)M1, qpi, ipb, img, w_ia, ictx,
                   part + (size_t)2*M1, part + (size_t)3*M1, qps, spb, sem, w_sa, sctx };
        att_both<<<512, 256>>>(A);
    }
    // 5: BIG2 — cat-f (2 chunks at 5M1,6M1) + cat-i (4 at 7M1..) + cat-s (11M1)
    {
        TaskList L{};
        for (int c = 0; c < 2; c++)
            L.t[c] = { h_r + 512*c, Wfg_r + (size_t)512*c*PP, nullptr, nullptr,
                       part + (size_t)(5 + c)*M1, IN_D, PP, 0, PP, ROWS, 512, 3, 0 };
        for (int c = 0; c < 4; c++)
            L.t[2 + c] = { ictx + 512*c, Wig_r + (size_t)512*c*PP, nullptr, nullptr,
                           part + (size_t)(7 + c)*M1, IMG_D, PP, 0, PP, ROWS, 512, 3, 0 };
        L.t[6] = { sctx, Wsg_r, nullptr, nullptr,
                   part + (size_t)11*M1, SEM_D, PP, 0, PP, ROWS, 512, 3, 0 };
        mma_gemm<<<dim3(4, 16, 7), 256, GEMM_SMEM>>>(L);
    }
    // 6: RED2 — assemble cat (bias + tf32-round)
    {
        RList L{};
        L.t[0] = { part + (size_t)5*M1,  2, M1, b_fg, nullptr, 0, cat,        CATD, ROWS, PP, 0, 1 };
        L.t[1] = { part + (size_t)7*M1,  4, M1, b_ig, nullptr, 0, cat + PP,   CATD, ROWS, PP, 0, 1 };
        L.t[2] = { part + (size_t)11*M1, 1, 0,  b_sg, nullptr, 0, cat + 2*PP, CATD, ROWS, PP, 0, 1 };
        reduce_k<<<dim3(256, 3), 256>>>(L);
    }
    // 7: BIG3 — gate in 3 K-chunks of 512 (576 CTAs = 2 clean waves)
    {
        TaskList L{};
        for (int c = 0; c < 3; c++)
            L.t[c] = { cat + 512*c, Wgate_r + (size_t)512*c*CATD, nullptr, nullptr,
                       part + (size_t)c*MG, CATD, CATD, 0, CATD, ROWS, 512, 3, 0 };
        mma_gemm<<<dim3(12, 16, 3), 256, GEMM_SMEM>>>(L);
    }
    // 8: REDG — gcat = tf32( sigmoid(sum3 + b_gate) * cat )
    {
        RList L{};
        L.t[0] = { part, 3, MG, b_gate, cat, CATD, gcat, CATD, ROWS, CATD, 2, 1 };
        reduce_k<<<dim3(256, 1), 256>>>(L);
    }
    // 9: BIG4 — out in 2 K-chunks of 768 (256 CTAs < 1 wave)
    {
        TaskList L{};
        for (int c = 0; c < 2; c++)
            L.t[c] = { gcat + 768*c, Wout_r + (size_t)768*c*OUTD, nullptr, nullptr,
                       part + (size_t)c*MO, CATD, OUTD, 0, OUTD, ROWS, 768, 3, 0 };
        mma_gemm<<<dim3(8, 16, 2), 256, GEMM_SMEM>>>(L);
    }
    // 10: RED3 — out = sum2 + bias
    {
        RList L{};
        L.t[0] = { part, 2, MO, b_out, nullptr, 0, out, OUTD, ROWS, OUTD, 0, 0 };
        reduce_k<<<dim3(256, 1), 256>>>(L);
    }
}